// round 7
// baseline (speedup 1.0000x reference)
#include <cuda_runtime.h>
#include <cuda_bf16.h>
#include <stdint.h>

#define HD 1024
#define TT 4096
#define NB0 32
#define NB12 57
#define GRIDN (NB0 + 2*NB12)   /* 146 persistent blocks */
#define NTHR 384
#define NW 12

#define OFF1 (NB0*128*1024)            /* 4194304  */
#define SEG12 (NB12*72*2048)           /* 8404992  */
#define OFF2 (OFF1 + SEG12)
#define WTOT (OFF1 + 2*SEG12)          /* 21004288 */

#define DSMEM_BYTES 172032             /* l12: 42 rows * 4096B ; l0 uses 62*2048 */

// ---------------- static device storage (no allocations) ----------------
__device__ __align__(16) __nv_bfloat16 g_wblob[WTOT];            // ~42 MB bf16 weights
__device__ float g_bias[NB0*128 + 2*NB12*72];
__device__ float g_wih0[NB0*128*2];
__device__ __align__(16) __nv_bfloat16 g_hall[(size_t)(TT+1)*3*HD]; // h history, write-once
__device__ __align__(128) int g_flag[3*64*32];                   // one 128B line per (layer,block)

// per-warp row tables (layer 0: 11 compute warps; layers 1/2: 10)
__constant__ int c_base0[11] = {0,12,24,36,49,60,71,82,95,106,117};
__constant__ int c_cnt0[11]  = {12,12,12,13,11,11,11,13,11,11,11};
__constant__ int c_sb0[11]   = {0,6,12,18,25,30,35,40,47,52,57};   /* prefix of cnt-6 */
__constant__ int c_base12[10] = {0,6,12,21,30,36,42,51,60,66};
__constant__ int c_cnt12[10]  = {6,6,9,9,6,6,9,9,6,6};
__constant__ int c_sb12[10]   = {0,3,6,12,18,21,24,30,36,39};      /* prefix of cnt-3 */

__device__ __forceinline__ __nv_bfloat162 u2b(unsigned u) {
    return *reinterpret_cast<const __nv_bfloat162*>(&u);
}
__device__ __forceinline__ float sigm(float v)  { return __fdividef(1.0f, 1.0f + __expf(-v)); }
__device__ __forceinline__ float ftanh(float v) {
    v = fminf(fmaxf(v, -30.0f), 30.0f);
    float e = __expf(2.0f*v);
    return __fdividef(e - 1.0f, e + 1.0f);
}
__device__ __forceinline__ int ld_acq(const int* p) {
    int v; asm volatile("ld.acquire.gpu.s32 %0, [%1];" : "=r"(v) : "l"(p) : "memory"); return v;
}
__device__ __forceinline__ void st_rel(int* p, int v) {
    asm volatile("st.release.gpu.s32 [%0], %1;" :: "l"(p), "r"(v) : "memory");
}

// whole-warp wait: padded flags (stride 32 ints = 128B), each lane owns <=2 flags
__device__ __forceinline__ void wait_flags_pad(const int* base, int nb, int target, int lane) {
    const int* p0 = base + (size_t)(lane < nb ? lane : 0)*32;
    const int* p1 = base + (size_t)((lane + 32 < nb) ? (lane + 32) : 0)*32;
    for (;;) {
        int v = min(ld_acq(p0), ld_acq(p1));
        if (__all_sync(0xffffffffu, v >= target)) break;
    }
}

// ---------------- prep: repack weights into per-block bf16 blobs ----------------
__global__ void prep_w(const float* __restrict__ Whh0,
                       const float* __restrict__ Wih12,
                       const float* __restrict__ Whh12)
{
    for (long long i = (long long)blockIdx.x*blockDim.x + threadIdx.x; i < (long long)WTOT;
         i += (long long)gridDim.x*blockDim.x) {
        float val;
        if (i < (long long)OFF1) {
            int b   = (int)(i >> 17);
            int rem = (int)(i & 131071);
            int r   = rem >> 10;
            int col = rem & 1023;
            int grow = (r & 3)*HD + b*32 + (r >> 2);
            val = Whh0[(long long)grow*1024 + col];
        } else {
            int l = (i < (long long)OFF2) ? 0 : 1;
            long long j = i - (l ? (long long)OFF2 : (long long)OFF1);
            int b   = (int)(j / 147456);
            int rem = (int)(j % 147456);
            int r   = rem >> 11;
            int col = rem & 2047;
            int ih  = r >> 2;
            int CHb = (b == NB12-1) ? 16 : 18;
            if (ih >= CHb) val = 0.0f;
            else {
                int grow = (r & 3)*HD + b*18 + ih;
                if (col < 1024) val = Wih12[(long long)l*4194304 + (long long)grow*1024 + col];
                else            val = Whh12[(long long)l*4194304 + (long long)grow*1024 + (col-1024)];
            }
        }
        g_wblob[i] = __float2bfloat16(val);
    }
}

// ---------------- prep: biases, W_ih0, state/flag reset ----------------
__global__ void prep_small(const float* __restrict__ Wih0,
                           const float* __restrict__ bih0, const float* __restrict__ bhh0,
                           const float* __restrict__ bih12, const float* __restrict__ bhh12)
{
    int i = blockIdx.x*blockDim.x + threadIdx.x;
    int n = blockDim.x*gridDim.x;
    for (int k = i; k < 3*64*32; k += n) g_flag[k] = 0;
    for (int k = i; k < 3*HD; k += n) g_hall[k] = __float2bfloat16(0.0f);
    for (int k = i; k < NB0*128 + 2*NB12*72; k += n) {
        float v;
        if (k < NB0*128) {
            int b = k >> 7, r = k & 127;
            int grow = (r & 3)*HD + b*32 + (r >> 2);
            v = bih0[grow] + bhh0[grow];
        } else {
            int j  = k - NB0*128;
            int l  = j / (NB12*72);
            int jj = j - l*(NB12*72);
            int b  = jj / 72, r = jj % 72;
            int ih = r >> 2;
            int CHb = (b == NB12-1) ? 16 : 18;
            if (ih >= CHb) v = 0.0f;
            else {
                int grow = (r & 3)*HD + b*18 + ih;
                v = bih12[l*4096 + grow] + bhh12[l*4096 + grow];
            }
        }
        g_bias[k] = v;
    }
    for (int k = i; k < NB0*128*2; k += n) {
        int b = k >> 8;
        int r = (k >> 1) & 127;
        int c = k & 1;
        int grow = (r & 3)*HD + b*32 + (r >> 2);
        g_wih0[k] = Wih0[grow*2 + c];
    }
}

// 16-HFMA2 partial dot: 4 weight u4 x 4 vector u4 (128 bf16 columns)
__device__ __forceinline__ float dot16(const uint4 w0, const uint4 w1, const uint4 w2, const uint4 w3,
                                       const uint4 v0, const uint4 v1, const uint4 v2, const uint4 v3)
{
    __nv_bfloat162 z = __floats2bfloat162_rn(0.0f, 0.0f);
    __nv_bfloat162 a0 = z, a1 = z, a2 = z, a3 = z;
    a0 = __hfma2(u2b(w0.x), u2b(v0.x), a0); a1 = __hfma2(u2b(w0.y), u2b(v0.y), a1);
    a2 = __hfma2(u2b(w0.z), u2b(v0.z), a2); a3 = __hfma2(u2b(w0.w), u2b(v0.w), a3);
    a0 = __hfma2(u2b(w1.x), u2b(v1.x), a0); a1 = __hfma2(u2b(w1.y), u2b(v1.y), a1);
    a2 = __hfma2(u2b(w1.z), u2b(v1.z), a2); a3 = __hfma2(u2b(w1.w), u2b(v1.w), a3);
    a0 = __hfma2(u2b(w2.x), u2b(v2.x), a0); a1 = __hfma2(u2b(w2.y), u2b(v2.y), a1);
    a2 = __hfma2(u2b(w2.z), u2b(v2.z), a2); a3 = __hfma2(u2b(w2.w), u2b(v2.w), a3);
    a0 = __hfma2(u2b(w3.x), u2b(v3.x), a0); a1 = __hfma2(u2b(w3.y), u2b(v3.y), a1);
    a2 = __hfma2(u2b(w3.z), u2b(v3.z), a2); a3 = __hfma2(u2b(w3.w), u2b(v3.w), a3);
    __nv_bfloat162 s2 = __hadd2(__hadd2(a0, a1), __hadd2(a2, a3));
    float2 f = __bfloat1622float2(s2);
    return f.x + f.y;
}

// ---------------- persistent dataflow LSTM kernel (barrier-free loop) ----------------
__global__ void __launch_bounds__(NTHR, 1) lstm_main(const float* __restrict__ x)
{
    extern __shared__ uint4 s_w4[];         // smem weight rows
    __shared__ uint4 s_vA[2][128];          // lower-h staging (layers 1/2), parity
    __shared__ uint4 s_vB[2][128];          // own-h staging, parity
    __shared__ float s_gates[2][128];
    __shared__ float s_bias[128];
    __shared__ float s_wih0[256];
    __shared__ volatile int s_readyA;       // lower-h staged up to (value)
    __shared__ volatile int s_readyO;       // own-h staged up to (value)
    __shared__ volatile int s_pub;          // own published up to (value)
    __shared__ int s_done[2];               // gate-completion counters per parity

    const int tid = threadIdx.x, lane = tid & 31, wid = tid >> 5;
    const int b = blockIdx.x;
    int layer, idx;
    if (b < NB0)             { layer = 0; idx = b; }
    else if (b < NB0+NB12)   { layer = 1; idx = b - NB0; }
    else                     { layer = 2; idx = b - (NB0+NB12); }

    int CH, hbase, R, rowU4, NBown, NBlow, boff, NCW;
    long long woff;
    if (layer == 0) {
        CH = 32; hbase = idx*32; R = 128; rowU4 = 128; NCW = 11;
        woff = (long long)idx*131072; boff = idx*128;
        NBown = NB0; NBlow = 0;
    } else {
        CH = (idx == NB12-1) ? 16 : 18; hbase = idx*18; R = 4*CH; rowU4 = 256; NCW = 10;
        woff = (long long)OFF1 + (long long)(layer-1)*SEG12 + (long long)idx*147456;
        boff = NB0*128 + (layer-1)*(NB12*72) + idx*72;
        NBown = NB12; NBlow = (layer == 1) ? NB0 : NB12;
    }
    const uint4* gw = (const uint4*)(g_wblob + woff);
    const uint4* hall4 = (const uint4*)g_hall;
    int* ownflags = &g_flag[layer*64*32];
    int* lowflags = &g_flag[(layer-1)*64*32];

    // per-warp row assignment
    int base = 0, cnt = 0, sbase = 0, sc = 0, rr = 0;
    bool is_compute = false;
    if (layer == 0) {
        if (wid < 11) { is_compute = true; base = c_base0[wid]; cnt = c_cnt0[wid];
                        sbase = c_sb0[wid]; rr = 6; sc = cnt - 6; }
    } else {
        if (wid < 10) { is_compute = true; base = c_base12[wid]; cnt = c_cnt12[wid];
                        sbase = c_sb12[wid]; rr = 3; sc = cnt - 3; }
    }

    // one-time weight staging: register rows + this warp's smem rows
    uint4 wreg[24];
    if (is_compute) {
        if (layer == 0) {
#pragma unroll
            for (int i2 = 0; i2 < 6; i2++)
#pragma unroll
                for (int j = 0; j < 4; j++)
                    wreg[i2*4+j] = gw[(size_t)(base+i2)*128 + j*32 + lane];
            for (int i2 = 0; i2 < sc; i2++)
#pragma unroll
                for (int j = 0; j < 4; j++)
                    s_w4[(size_t)(sbase+i2)*128 + j*32 + lane] = gw[(size_t)(base+6+i2)*128 + j*32 + lane];
        } else {
#pragma unroll
            for (int i2 = 0; i2 < 3; i2++)
#pragma unroll
                for (int j = 0; j < 8; j++)
                    wreg[i2*8+j] = gw[(size_t)(base+i2)*256 + j*32 + lane];
            for (int i2 = 0; i2 < sc; i2++)
#pragma unroll
                for (int j = 0; j < 8; j++)
                    s_w4[(size_t)(sbase+i2)*256 + j*32 + lane] = gw[(size_t)(base+3+i2)*256 + j*32 + lane];
        }
    }
    if (tid < R) s_bias[tid] = g_bias[boff + tid];
    if (layer == 0 && tid < 256) s_wih0[tid] = g_wih0[idx*256 + tid];
    if (tid == 0) { s_readyA = 0; s_readyO = 0; s_pub = 0; s_done[0] = 0; s_done[1] = 0; }
    float creg = 0.0f;
    __syncthreads();

    for (int t = 0; t < TT; ++t) {
        const int p = t & 1;

        if (wid == NW-1) {
            // ---- orchestrator: own-flag poll, own-h stage, pointwise, publish ----
            wait_flags_pad(ownflags, NBown, t, lane);
            size_t hoff = (size_t)t*384 + (size_t)layer*128;
            s_vB[p][lane]    = hall4[hoff + lane];
            s_vB[p][lane+32] = hall4[hoff + lane + 32];
            s_vB[p][lane+64] = hall4[hoff + lane + 64];
            s_vB[p][lane+96] = hall4[hoff + lane + 96];
            __threadfence_block();
            if (lane == 0) s_readyO = t + 1;
            if (lane == 0) { while (*(volatile int*)&s_done[p] != NCW) { } }
            __syncwarp();
            __threadfence_block();
            if (lane == 0) s_done[p] = 0;
            if (lane < CH) {
                float4 g = ((const float4*)s_gates[p])[lane];
                float ig = sigm(g.x);
                float fg = sigm(g.y);
                float gv = ftanh(g.z);
                float og = sigm(g.w);
                float c  = fg*creg + ig*gv;
                creg = c;
                g_hall[(size_t)(t+1)*3072 + (size_t)layer*1024 + hbase + lane] =
                    __float2bfloat16(og*ftanh(c));
            }
            __syncwarp();
            if (lane == 0) { st_rel(&ownflags[idx*32], t + 1); s_pub = t + 1; }
        }
        else if (layer > 0 && wid == NW-2) {
            // ---- lower-h poller/stager ----
            if (t >= 2) { while (s_pub < t - 1) { } }          // buffer-consumed guard
            wait_flags_pad(lowflags, NBlow, t + 1, lane);
            size_t loff = (size_t)(t+1)*384 + (size_t)(layer-1)*128;
            s_vA[p][lane]    = hall4[loff + lane];
            s_vA[p][lane+32] = hall4[loff + lane + 32];
            s_vA[p][lane+64] = hall4[loff + lane + 64];
            s_vA[p][lane+96] = hall4[loff + lane + 96];
            __threadfence_block();
            if (lane == 0) s_readyA = t + 1;
        }
        else if (is_compute) {
            float ss[13];
            if (layer == 0) {
                float x0 = __ldg(&x[2*t]), x1 = __ldg(&x[2*t + 1]);
                while (s_readyO < t + 1) { }
                __threadfence_block();
                uint4 v0 = s_vB[p][lane], v1 = s_vB[p][32+lane],
                      v2 = s_vB[p][64+lane], v3 = s_vB[p][96+lane];
#pragma unroll
                for (int i2 = 0; i2 < 6; i2++)
                    ss[i2] = dot16(wreg[i2*4], wreg[i2*4+1], wreg[i2*4+2], wreg[i2*4+3],
                                   v0, v1, v2, v3);
#pragma unroll
                for (int i2 = 0; i2 < 7; i2++) {
                    if (i2 < sc) {
                        const uint4* wp = s_w4 + (size_t)(sbase+i2)*128;
                        ss[6+i2] = dot16(wp[lane], wp[32+lane], wp[64+lane], wp[96+lane],
                                         v0, v1, v2, v3);
                    }
                }
#pragma unroll
                for (int o = 16; o; o >>= 1)
#pragma unroll
                    for (int k = 0; k < 13; k++)
                        if (k < cnt) ss[k] += __shfl_xor_sync(0xffffffffu, ss[k], o);
                if (lane == 0) {
#pragma unroll
                    for (int k = 0; k < 13; k++) {
                        if (k < cnt) {
                            int r = base + k;
                            s_gates[p][r] = ss[k] + s_bias[r] + s_wih0[2*r]*x0 + s_wih0[2*r+1]*x1;
                        }
                    }
                }
            } else {
                // phase A: lower-h half (columns 0..1023)
                while (s_readyA < t + 1) { }
                __threadfence_block();
                {
                    uint4 v0 = s_vA[p][lane], v1 = s_vA[p][32+lane],
                          v2 = s_vA[p][64+lane], v3 = s_vA[p][96+lane];
#pragma unroll
                    for (int i2 = 0; i2 < 3; i2++)
                        ss[i2] = dot16(wreg[i2*8], wreg[i2*8+1], wreg[i2*8+2], wreg[i2*8+3],
                                       v0, v1, v2, v3);
#pragma unroll
                    for (int i2 = 0; i2 < 6; i2++) {
                        if (i2 < sc) {
                            const uint4* wp = s_w4 + (size_t)(sbase+i2)*256;
                            ss[3+i2] = dot16(wp[lane], wp[32+lane], wp[64+lane], wp[96+lane],
                                             v0, v1, v2, v3);
                        }
                    }
                }
                // phase B: own-h half (columns 1024..2047)
                while (s_readyO < t + 1) { }
                __threadfence_block();
                {
                    uint4 v0 = s_vB[p][lane], v1 = s_vB[p][32+lane],
                          v2 = s_vB[p][64+lane], v3 = s_vB[p][96+lane];
#pragma unroll
                    for (int i2 = 0; i2 < 3; i2++)
                        ss[i2] += dot16(wreg[i2*8+4], wreg[i2*8+5], wreg[i2*8+6], wreg[i2*8+7],
                                        v0, v1, v2, v3);
#pragma unroll
                    for (int i2 = 0; i2 < 6; i2++) {
                        if (i2 < sc) {
                            const uint4* wp = s_w4 + (size_t)(sbase+i2)*256 + 128;
                            ss[3+i2] += dot16(wp[lane], wp[32+lane], wp[64+lane], wp[96+lane],
                                              v0, v1, v2, v3);
                        }
                    }
                }
#pragma unroll
                for (int o = 16; o; o >>= 1)
#pragma unroll
                    for (int k = 0; k < 9; k++)
                        if (k < cnt) ss[k] += __shfl_xor_sync(0xffffffffu, ss[k], o);
                if (lane == 0) {
#pragma unroll
                    for (int k = 0; k < 9; k++) {
                        if (k < cnt) {
                            int r = base + k;
                            s_gates[p][r] = ss[k] + s_bias[r];
                        }
                    }
                }
            }
            __threadfence_block();
            if (lane == 0) atomicAdd(&s_done[p], 1);
        }
    }
}

// ---------------- output head ----------------
__global__ void finalize_k(const float* __restrict__ Wres, const float* __restrict__ bres,
                           float* __restrict__ out)
{
    __shared__ float sred[4];
    const int t = blockIdx.x;
    const int tid = threadIdx.x;
    const __nv_bfloat16* h = g_hall + (size_t)(t+1)*3072 + 2048;
    float s = 0.0f;
    for (int k = tid; k < HD; k += 128) s += __bfloat162float(h[k]) * Wres[k];
#pragma unroll
    for (int o = 16; o; o >>= 1) s += __shfl_xor_sync(0xffffffffu, s, o);
    if ((tid & 31) == 0) sred[tid >> 5] = s;
    __syncthreads();
    if (tid == 0) {
        float tot = sred[0] + sred[1] + sred[2] + sred[3];
        out[t] = 1.0f/(1.0f + __expf(-(tot + bres[0])));
    }
}

// ---------------- launch ----------------
extern "C" void kernel_launch(void* const* d_in, const int* in_sizes, int n_in,
                              void* d_out, int out_size)
{
    const float* x     = (const float*)d_in[0];
    const float* Wih0  = (const float*)d_in[1];
    const float* Whh0  = (const float*)d_in[2];
    const float* bih0  = (const float*)d_in[3];
    const float* bhh0  = (const float*)d_in[4];
    const float* Wih12 = (const float*)d_in[5];
    const float* Whh12 = (const float*)d_in[6];
    const float* bih12 = (const float*)d_in[7];
    const float* bhh12 = (const float*)d_in[8];
    const float* Wres  = (const float*)d_in[9];
    const float* bres  = (const float*)d_in[10];
    float* out = (float*)d_out;

    cudaFuncSetAttribute(lstm_main, cudaFuncAttributeMaxDynamicSharedMemorySize, DSMEM_BYTES);

    prep_small<<<26, 256>>>(Wih0, bih0, bhh0, bih12, bhh12);
    prep_w<<<2048, 256>>>(Whh0, Wih12, Whh12);
    lstm_main<<<GRIDN, NTHR, DSMEM_BYTES>>>(x);
    finalize_k<<<TT, 128>>>(Wres, bres, out);
}

// round 8
// speedup vs baseline: 1.0947x; 1.0947x over previous
#include <cuda_runtime.h>
#include <cuda_bf16.h>
#include <stdint.h>

#define HD 1024
#define TT 4096
#define NB0 36
#define NB12 56
#define GRIDN 148
#define NTHR 384
#define NCW 11                          /* compute warps per block */

#define L0SZ  4194304ull                /* 4096*1024 bf16 */
#define L12SZ 8388608ull                /* 4096*2048 bf16 */
#define WTOT  (L0SZ + 2ull*L12SZ)       /* 20971520 */

#define DSMEM_BYTES 176128              /* l12 worst: 43 rows * 4096B */

// ---------------- static device storage ----------------
__device__ __align__(16) __nv_bfloat16 g_wblob[WTOT];               // 42 MB canonical weights
__device__ float g_bias[3*4096];                                    // packed fused biases
__device__ float g_wih0[4096*2];                                    // layer0 W_ih packed
__device__ __align__(16) __nv_bfloat16 g_hall[(size_t)(TT+1)*3*HD]; // h history
__device__ __align__(128) int g_flag[3*64*32];                      // 128B line per (layer,block)

__device__ __forceinline__ __nv_bfloat162 u2b(unsigned u) {
    return *reinterpret_cast<const __nv_bfloat162*>(&u);
}
__device__ __forceinline__ float sigm(float v)  { return __fdividef(1.0f, 1.0f + __expf(-v)); }
__device__ __forceinline__ float ftanh(float v) {
    v = fminf(fmaxf(v, -30.0f), 30.0f);
    float e = __expf(2.0f*v);
    return __fdividef(e - 1.0f, e + 1.0f);
}
__device__ __forceinline__ int ld_acq(const int* p) {
    int v; asm volatile("ld.acquire.gpu.s32 %0, [%1];" : "=r"(v) : "l"(p) : "memory"); return v;
}

// whole-warp wait: padded flags (128B apart), each lane owns <=2 flags
__device__ __forceinline__ void wait_flags_pad(const int* base, int nb, int target, int lane) {
    const int* p0 = base + (size_t)(lane < nb ? lane : 0)*32;
    const int* p1 = base + (size_t)((lane + 32 < nb) ? (lane + 32) : 0)*32;
    for (;;) {
        int v = min(ld_acq(p0), ld_acq(p1));
        if (__all_sync(0xffffffffu, v >= target)) break;
    }
}

// ---------------- prep: canonical channel-ordered bf16 blob ----------------
__global__ void prep_w(const float* __restrict__ Whh0,
                       const float* __restrict__ Wih12,
                       const float* __restrict__ Whh12)
{
    for (long long i = (long long)blockIdx.x*blockDim.x + threadIdx.x; i < (long long)WTOT;
         i += (long long)gridDim.x*blockDim.x) {
        float val;
        if (i < (long long)L0SZ) {
            int row = (int)(i >> 10);            // packed row = ch*4 + g
            int col = (int)(i & 1023);
            int ch = row >> 2, g = row & 3;
            val = Whh0[(long long)(g*HD + ch)*1024 + col];
        } else {
            long long j = i - (long long)L0SZ;
            int l = (int)(j / (long long)L12SZ);
            long long r = j % (long long)L12SZ;
            int row = (int)(r >> 11);
            int col = (int)(r & 2047);
            int ch = row >> 2, g = row & 3;
            long long grow = (long long)l*4194304ll + (long long)(g*HD + ch)*1024;
            val = (col < 1024) ? Wih12[grow + col] : Whh12[grow + (col - 1024)];
        }
        g_wblob[i] = __float2bfloat16(val);
    }
}

__global__ void prep_small(const float* __restrict__ Wih0,
                           const float* __restrict__ bih0, const float* __restrict__ bhh0,
                           const float* __restrict__ bih12, const float* __restrict__ bhh12)
{
    int i = blockIdx.x*blockDim.x + threadIdx.x;
    int n = blockDim.x*gridDim.x;
    for (int k = i; k < 3*64*32; k += n) g_flag[k] = 0;
    for (int k = i; k < 3*HD; k += n) g_hall[k] = __float2bfloat16(0.0f);
    for (int k = i; k < 3*4096; k += n) {
        float v;
        if (k < 4096) {
            int ch = k >> 2, g = k & 3;
            v = bih0[g*HD + ch] + bhh0[g*HD + ch];
        } else {
            int l = (k - 4096) >> 12;
            int row = (k - 4096) & 4095;
            int ch = row >> 2, g = row & 3;
            v = bih12[l*4096 + g*HD + ch] + bhh12[l*4096 + g*HD + ch];
        }
        g_bias[k] = v;
    }
    for (int k = i; k < 4096*2; k += n) {
        int row = k >> 1, c = k & 1;
        int ch = row >> 2, g = row & 3;
        g_wih0[k] = Wih0[(g*HD + ch)*2 + c];
    }
}

// 16-HFMA2 partial dot: 4 weight u4 x 4 vector u4 (128 bf16 columns)
__device__ __forceinline__ float dot16(const uint4 w0, const uint4 w1, const uint4 w2, const uint4 w3,
                                       const uint4 v0, const uint4 v1, const uint4 v2, const uint4 v3)
{
    __nv_bfloat162 z = __floats2bfloat162_rn(0.0f, 0.0f);
    __nv_bfloat162 a0 = z, a1 = z, a2 = z, a3 = z;
    a0 = __hfma2(u2b(w0.x), u2b(v0.x), a0); a1 = __hfma2(u2b(w0.y), u2b(v0.y), a1);
    a2 = __hfma2(u2b(w0.z), u2b(v0.z), a2); a3 = __hfma2(u2b(w0.w), u2b(v0.w), a3);
    a0 = __hfma2(u2b(w1.x), u2b(v1.x), a0); a1 = __hfma2(u2b(w1.y), u2b(v1.y), a1);
    a2 = __hfma2(u2b(w1.z), u2b(v1.z), a2); a3 = __hfma2(u2b(w1.w), u2b(v1.w), a3);
    a0 = __hfma2(u2b(w2.x), u2b(v2.x), a0); a1 = __hfma2(u2b(w2.y), u2b(v2.y), a1);
    a2 = __hfma2(u2b(w2.z), u2b(v2.z), a2); a3 = __hfma2(u2b(w2.w), u2b(v2.w), a3);
    a0 = __hfma2(u2b(w3.x), u2b(v3.x), a0); a1 = __hfma2(u2b(w3.y), u2b(v3.y), a1);
    a2 = __hfma2(u2b(w3.z), u2b(v3.z), a2); a3 = __hfma2(u2b(w3.w), u2b(v3.w), a3);
    __nv_bfloat162 s2 = __hadd2(__hadd2(a0, a1), __hadd2(a2, a3));
    float2 f = __bfloat1622float2(s2);
    return f.x + f.y;
}

// ---------------- persistent split-phase LSTM kernel ----------------
__global__ void __launch_bounds__(NTHR, 1) lstm_main(const float* __restrict__ x)
{
    extern __shared__ uint4 s_w4[];
    __shared__ uint4 s_vA[2][128];      // lower-h (l1/l2)
    __shared__ uint4 s_vB[2][128];      // own-h

    const int tid = threadIdx.x, lane = tid & 31, wid = tid >> 5;
    const int b = blockIdx.x;
    int layer, idx;
    if (b < NB0)             { layer = 0; idx = b; }
    else if (b < NB0+NB12)   { layer = 1; idx = b - NB0; }
    else                     { layer = 2; idx = b - (NB0+NB12); }

    int CH, chbase, boff, NBown, NBlow;
    size_t weoff;
    if (layer == 0) {
        CH = 28 + (idx < 16); chbase = idx*28 + min(idx, 16);
        weoff = (size_t)(chbase*4)*1024; boff = 0;
        NBown = NB0; NBlow = 0;
    } else {
        CH = 18 + (idx < 16); chbase = idx*18 + min(idx, 16);
        weoff = L0SZ + (size_t)(layer-1)*L12SZ + (size_t)(chbase*4)*2048;
        boff = 4096 + (layer-1)*4096;
        NBown = NB12; NBlow = (layer == 1) ? NB0 : NB12;
    }
    const uint4* gw = (const uint4*)(g_wblob) + (weoff >> 3);
    const uint4* hall4 = (const uint4*)g_hall;
    int* ownflags = &g_flag[layer*64*32];
    int* lowflags = &g_flag[(layer-1)*64*32];

    // compute-warp channel assignment (warps 1..11)
    const bool isc = (wid >= 1);
    const int w1 = wid - 1;
    const int basen = (layer == 0) ? 2 : 1;
    const int REGR  = (layer == 0) ? 6 : 3;
    const int extra = CH - basen*NCW;
    int nch = 0, chw = 0, rows = 0, regn = 0, scn = 0, sbase = 0;
    if (isc) {
        nch = basen + (w1 < extra ? 1 : 0);
        chw = basen*w1 + min(w1, extra);
        rows = 4*nch; regn = min(rows, REGR); scn = rows - regn;
        for (int q = 0; q < w1; q++) {
            int rq = 4*(basen + (q < extra ? 1 : 0));
            sbase += max(0, rq - REGR);
        }
    }

    // one-time weight staging
    uint4 wreg[24];
    if (isc) {
        if (layer == 0) {
#pragma unroll
            for (int k = 0; k < 6; k++) if (k < regn)
#pragma unroll
                for (int j = 0; j < 4; j++)
                    wreg[k*4+j] = gw[(size_t)(chw*4+k)*128 + j*32 + lane];
            for (int k = 0; k < scn; k++)
#pragma unroll
                for (int j = 0; j < 4; j++)
                    s_w4[(size_t)(sbase+k)*128 + j*32 + lane] = gw[(size_t)(chw*4+regn+k)*128 + j*32 + lane];
        } else {
#pragma unroll
            for (int k = 0; k < 3; k++) if (k < regn)
#pragma unroll
                for (int j = 0; j < 8; j++)
                    wreg[k*8+j] = gw[(size_t)(chw*4+k)*256 + j*32 + lane];
            for (int k = 0; k < scn; k++)
#pragma unroll
                for (int j = 0; j < 8; j++)
                    s_w4[(size_t)(sbase+k)*256 + j*32 + lane] = gw[(size_t)(chw*4+regn+k)*256 + j*32 + lane];
        }
    }
    // per-lane channel constants (lane j < nch owns channel chw+j)
    float4 bj = make_float4(0.f,0.f,0.f,0.f);
    float4 wxa = bj, wxb = bj;
    float creg = 0.0f;
    if (isc && lane < nch) {
        int arow = (chbase + chw + lane)*4;
        bj = *(const float4*)&g_bias[boff + arow];
        if (layer == 0) {
            wxa = *(const float4*)&g_wih0[arow*2];
            wxb = *(const float4*)&g_wih0[arow*2 + 4];
        }
    }
    __syncthreads();

    for (int t = 0; t < TT; ++t) {
        const int p = t & 1;
        float ss[12];

        if (layer == 0) {
            float x0 = x[2*t], x1 = x[2*t + 1];
            if (wid == 0) {
                wait_flags_pad(ownflags, NBown, NCW*t, lane);
                size_t ho = (size_t)t*384;
                s_vB[p][lane]    = hall4[ho + lane];
                s_vB[p][lane+32] = hall4[ho + lane + 32];
                s_vB[p][lane+64] = hall4[ho + lane + 64];
                s_vB[p][lane+96] = hall4[ho + lane + 96];
            }
            __syncthreads();
            if (isc) {
                uint4 v0 = s_vB[p][lane], v1 = s_vB[p][32+lane],
                      v2 = s_vB[p][64+lane], v3 = s_vB[p][96+lane];
#pragma unroll
                for (int k = 0; k < 6; k++) if (k < regn)
                    ss[k] = dot16(wreg[k*4], wreg[k*4+1], wreg[k*4+2], wreg[k*4+3], v0, v1, v2, v3);
#pragma unroll
                for (int k = 0; k < 6; k++) if (k < scn) {
                    const uint4* wp = s_w4 + (size_t)(sbase+k)*128;
                    ss[regn+k] = dot16(wp[lane], wp[32+lane], wp[64+lane], wp[96+lane], v0, v1, v2, v3);
                }
#pragma unroll
                for (int o = 16; o; o >>= 1)
#pragma unroll
                    for (int k = 0; k < 12; k++)
                        if (k < rows) ss[k] += __shfl_xor_sync(0xffffffffu, ss[k], o);
                if (lane < nch) {
                    float gi = ss[0], gf = ss[1], gg = ss[2], go = ss[3];
                    if (lane == 1) { gi = ss[4]; gf = ss[5]; gg = ss[6];  go = ss[7]; }
                    if (lane == 2) { gi = ss[8]; gf = ss[9]; gg = ss[10]; go = ss[11]; }
                    gi += bj.x + wxa.x*x0 + wxa.y*x1;
                    gf += bj.y + wxa.z*x0 + wxa.w*x1;
                    gg += bj.z + wxb.x*x0 + wxb.y*x1;
                    go += bj.w + wxb.z*x0 + wxb.w*x1;
                    float c = sigm(gf)*creg + sigm(gi)*ftanh(gg);
                    creg = c;
                    g_hall[(size_t)(t+1)*3072 + chbase + chw + lane] =
                        __float2bfloat16(sigm(go)*ftanh(c));
                }
                __syncwarp();
                if (lane == 0) {
                    __threadfence();
                    asm volatile("red.release.gpu.global.add.s32 [%0], %1;"
                                 :: "l"(&ownflags[idx*32]), "r"(1) : "memory");
                }
            }
        } else {
            // ---- phase A: lower-h (W_ih half), overlapped with own-flag wait ----
            if (wid == 1) {
                wait_flags_pad(lowflags, NBlow, NCW*(t+1), lane);
                size_t lo = (size_t)(t+1)*384 + (size_t)(layer-1)*128;
                s_vA[p][lane]    = hall4[lo + lane];
                s_vA[p][lane+32] = hall4[lo + lane + 32];
                s_vA[p][lane+64] = hall4[lo + lane + 64];
                s_vA[p][lane+96] = hall4[lo + lane + 96];
                asm volatile("bar.sync 1, 352;" ::: "memory");
            } else if (wid >= 2) {
                asm volatile("bar.sync 1, 352;" ::: "memory");
            }
            if (isc) {
                uint4 v0 = s_vA[p][lane], v1 = s_vA[p][32+lane],
                      v2 = s_vA[p][64+lane], v3 = s_vA[p][96+lane];
#pragma unroll
                for (int k = 0; k < 3; k++) if (k < regn)
                    ss[k] = dot16(wreg[k*8], wreg[k*8+1], wreg[k*8+2], wreg[k*8+3], v0, v1, v2, v3);
#pragma unroll
                for (int k = 0; k < 5; k++) if (k < scn) {
                    const uint4* wp = s_w4 + (size_t)(sbase+k)*256;
                    ss[regn+k] = dot16(wp[lane], wp[32+lane], wp[64+lane], wp[96+lane], v0, v1, v2, v3);
                }
            }
            if (wid == 0) {
                wait_flags_pad(ownflags, NBown, NCW*t, lane);
                size_t ho = (size_t)t*384 + (size_t)layer*128;
                s_vB[p][lane]    = hall4[ho + lane];
                s_vB[p][lane+32] = hall4[ho + lane + 32];
                s_vB[p][lane+64] = hall4[ho + lane + 64];
                s_vB[p][lane+96] = hall4[ho + lane + 96];
            }
            __syncthreads();
            // ---- phase B: own-h (W_hh half) — the recurrence-critical part ----
            if (isc) {
                uint4 v0 = s_vB[p][lane], v1 = s_vB[p][32+lane],
                      v2 = s_vB[p][64+lane], v3 = s_vB[p][96+lane];
#pragma unroll
                for (int k = 0; k < 3; k++) if (k < regn)
                    ss[k] += dot16(wreg[k*8+4], wreg[k*8+5], wreg[k*8+6], wreg[k*8+7], v0, v1, v2, v3);
#pragma unroll
                for (int k = 0; k < 5; k++) if (k < scn) {
                    const uint4* wp = s_w4 + (size_t)(sbase+k)*256 + 128;
                    ss[regn+k] += dot16(wp[lane], wp[32+lane], wp[64+lane], wp[96+lane], v0, v1, v2, v3);
                }
#pragma unroll
                for (int o = 16; o; o >>= 1)
#pragma unroll
                    for (int k = 0; k < 8; k++)
                        if (k < rows) ss[k] += __shfl_xor_sync(0xffffffffu, ss[k], o);
                if (lane < nch) {
                    float gi = ss[0], gf = ss[1], gg = ss[2], go = ss[3];
                    if (lane == 1) { gi = ss[4]; gf = ss[5]; gg = ss[6]; go = ss[7]; }
                    gi += bj.x; gf += bj.y; gg += bj.z; go += bj.w;
                    float c = sigm(gf)*creg + sigm(gi)*ftanh(gg);
                    creg = c;
                    g_hall[(size_t)(t+1)*3072 + (size_t)layer*1024 + chbase + chw + lane] =
                        __float2bfloat16(sigm(go)*ftanh(c));
                }
                __syncwarp();
                if (lane == 0) {
                    __threadfence();
                    asm volatile("red.release.gpu.global.add.s32 [%0], %1;"
                                 :: "l"(&ownflags[idx*32]), "r"(1) : "memory");
                }
            }
        }
    }
}

// ---------------- output head ----------------
__global__ void finalize_k(const float* __restrict__ Wres, const float* __restrict__ bres,
                           float* __restrict__ out)
{
    __shared__ float sred[4];
    const int t = blockIdx.x;
    const int tid = threadIdx.x;
    const __nv_bfloat16* h = g_hall + (size_t)(t+1)*3072 + 2048;
    float s = 0.0f;
    for (int k = tid; k < HD; k += 128) s += __bfloat162float(h[k]) * Wres[k];
#pragma unroll
    for (int o = 16; o; o >>= 1) s += __shfl_xor_sync(0xffffffffu, s, o);
    if ((tid & 31) == 0) sred[tid >> 5] = s;
    __syncthreads();
    if (tid == 0) {
        float tot = sred[0] + sred[1] + sred[2] + sred[3];
        out[t] = 1.0f/(1.0f + __expf(-(tot + bres[0])));
    }
}

// ---------------- launch ----------------
extern "C" void kernel_launch(void* const* d_in, const int* in_sizes, int n_in,
                              void* d_out, int out_size)
{
    const float* x     = (const float*)d_in[0];
    const float* Wih0  = (const float*)d_in[1];
    const float* Whh0  = (const float*)d_in[2];
    const float* bih0  = (const float*)d_in[3];
    const float* bhh0  = (const float*)d_in[4];
    const float* Wih12 = (const float*)d_in[5];
    const float* Whh12 = (const float*)d_in[6];
    const float* bih12 = (const float*)d_in[7];
    const float* bhh12 = (const float*)d_in[8];
    const float* Wres  = (const float*)d_in[9];
    const float* bres  = (const float*)d_in[10];
    float* out = (float*)d_out;

    cudaFuncSetAttribute(lstm_main, cudaFuncAttributeMaxDynamicSharedMemorySize, DSMEM_BYTES);

    prep_small<<<26, 256>>>(Wih0, bih0, bhh0, bih12, bhh12);
    prep_w<<<2048, 256>>>(Whh0, Wih12, Whh12);
    lstm_main<<<GRIDN, NTHR, DSMEM_BYTES>>>(x);
    finalize_k<<<TT, 128>>>(Wres, bres, out);
}

// round 9
// speedup vs baseline: 1.8463x; 1.6866x over previous
#include <cuda_runtime.h>
#include <cuda_bf16.h>
#include <stdint.h>

#define HD 1024
#define TT 4096
#define NB0 32
#define NB12 57
#define GRIDN (NB0 + 2*NB12)   /* 146 persistent blocks */
#define NTHR 384
#define NW 12                  /* warps per block */

#define OFF1 (NB0*128*1024)            /* 4194304  */
#define SEG12 (NB12*72*2048)           /* 8404992  */
#define OFF2 (OFF1 + SEG12)
#define WTOT (OFF1 + 2*SEG12)          /* 21004288 */

#define DSMEM_BYTES 196608             /* l12: 48 rows*4KB ; l0: 80 rows*2KB=160KB */

// ---------------- static device storage (no allocations) ----------------
__device__ __align__(16) __nv_bfloat16 g_wblob[WTOT];            // ~42 MB bf16 weights
__device__ float g_bias[NB0*128 + 2*NB12*72];
__device__ float g_wih0[NB0*128*2];
__device__ __align__(16) __nv_bfloat16 g_hall[(size_t)(TT+1)*3*HD]; // h history, write-once
__device__ __align__(128) int g_flag[3*64*32];                   // one 128B line per (layer,block)

__device__ __forceinline__ __nv_bfloat162 u2b(unsigned u) {
    return *reinterpret_cast<const __nv_bfloat162*>(&u);
}
__device__ __forceinline__ float sigm(float v)  { return __fdividef(1.0f, 1.0f + __expf(-v)); }
__device__ __forceinline__ float ftanh(float v) {
    v = fminf(fmaxf(v, -30.0f), 30.0f);
    float e = __expf(2.0f*v);
    return __fdividef(e - 1.0f, e + 1.0f);
}
__device__ __forceinline__ int ld_acq(const int* p) {
    int v; asm volatile("ld.acquire.gpu.s32 %0, [%1];" : "=r"(v) : "l"(p) : "memory"); return v;
}
__device__ __forceinline__ void st_rel(int* p, int v) {
    asm volatile("st.release.gpu.s32 [%0], %1;" :: "l"(p), "r"(v) : "memory");
}

// whole-warp wait: padded flags (stride 32 ints = 128B), each lane owns <=2 flags
__device__ __forceinline__ void wait_flags_pad(const int* base, int nb, int target, int lane) {
    const int* p0 = base + (size_t)(lane < nb ? lane : 0)*32;
    const int* p1 = base + (size_t)((lane + 32 < nb) ? (lane + 32) : 0)*32;
    for (;;) {
        int v = min(ld_acq(p0), ld_acq(p1));
        if (__all_sync(0xffffffffu, v >= target)) break;
    }
}

// ---------------- prep: repack weights into per-block bf16 blobs ----------------
__global__ void prep_w(const float* __restrict__ Whh0,
                       const float* __restrict__ Wih12,
                       const float* __restrict__ Whh12)
{
    for (long long i = (long long)blockIdx.x*blockDim.x + threadIdx.x; i < (long long)WTOT;
         i += (long long)gridDim.x*blockDim.x) {
        float val;
        if (i < (long long)OFF1) {
            int b   = (int)(i >> 17);
            int rem = (int)(i & 131071);
            int r   = rem >> 10;
            int col = rem & 1023;
            int grow = (r & 3)*HD + b*32 + (r >> 2);
            val = Whh0[(long long)grow*1024 + col];
        } else {
            int l = (i < (long long)OFF2) ? 0 : 1;
            long long j = i - (l ? (long long)OFF2 : (long long)OFF1);
            int b   = (int)(j / 147456);
            int rem = (int)(j % 147456);
            int r   = rem >> 11;
            int col = rem & 2047;
            int ih  = r >> 2;
            int CHb = (b == NB12-1) ? 16 : 18;
            if (ih >= CHb) val = 0.0f;
            else {
                int grow = (r & 3)*HD + b*18 + ih;
                if (col < 1024) val = Wih12[(long long)l*4194304 + (long long)grow*1024 + col];
                else            val = Whh12[(long long)l*4194304 + (long long)grow*1024 + (col-1024)];
            }
        }
        g_wblob[i] = __float2bfloat16(val);
    }
}

// ---------------- prep: biases, W_ih0, state/flag reset ----------------
__global__ void prep_small(const float* __restrict__ Wih0,
                           const float* __restrict__ bih0, const float* __restrict__ bhh0,
                           const float* __restrict__ bih12, const float* __restrict__ bhh12)
{
    int i = blockIdx.x*blockDim.x + threadIdx.x;
    int n = blockDim.x*gridDim.x;
    for (int k = i; k < 3*64*32; k += n) g_flag[k] = 0;
    for (int k = i; k < 3*HD; k += n) g_hall[k] = __float2bfloat16(0.0f);
    for (int k = i; k < NB0*128 + 2*NB12*72; k += n) {
        float v;
        if (k < NB0*128) {
            int b = k >> 7, r = k & 127;
            int grow = (r & 3)*HD + b*32 + (r >> 2);
            v = bih0[grow] + bhh0[grow];
        } else {
            int j  = k - NB0*128;
            int l  = j / (NB12*72);
            int jj = j - l*(NB12*72);
            int b  = jj / 72, r = jj % 72;
            int ih = r >> 2;
            int CHb = (b == NB12-1) ? 16 : 18;
            if (ih >= CHb) v = 0.0f;
            else {
                int grow = (r & 3)*HD + b*18 + ih;
                v = bih12[l*4096 + grow] + bhh12[l*4096 + grow];
            }
        }
        g_bias[k] = v;
    }
    for (int k = i; k < NB0*128*2; k += n) {
        int b = k >> 8;
        int r = (k >> 1) & 127;
        int c = k & 1;
        int grow = (r & 3)*HD + b*32 + (r >> 2);
        g_wih0[k] = Wih0[grow*2 + c];
    }
}

// ---------------- dot-product primitives (bf16x2 HFMA2) ----------------
template<int NJ>
__device__ __forceinline__ float dot_rr(const uint4* __restrict__ w, const uint4* __restrict__ v)
{
    __nv_bfloat162 z = __floats2bfloat162_rn(0.0f, 0.0f);
    __nv_bfloat162 a0 = z, a1 = z, a2 = z, a3 = z;
#pragma unroll
    for (int j = 0; j < NJ; j++) {
        a0 = __hfma2(u2b(w[j].x), u2b(v[j].x), a0);
        a1 = __hfma2(u2b(w[j].y), u2b(v[j].y), a1);
        a2 = __hfma2(u2b(w[j].z), u2b(v[j].z), a2);
        a3 = __hfma2(u2b(w[j].w), u2b(v[j].w), a3);
    }
    __nv_bfloat162 s2 = __hadd2(__hadd2(a0, a1), __hadd2(a2, a3));
    float2 f = __bfloat1622float2(s2);
    return f.x + f.y;
}

template<int NJ>
__device__ __forceinline__ float dot_sm(const uint4* __restrict__ wbase, int lane, const uint4* __restrict__ v)
{
    __nv_bfloat162 z = __floats2bfloat162_rn(0.0f, 0.0f);
    __nv_bfloat162 a0 = z, a1 = z, a2 = z, a3 = z;
#pragma unroll
    for (int j = 0; j < NJ; j++) {
        uint4 w = wbase[j*32 + lane];
        a0 = __hfma2(u2b(w.x), u2b(v[j].x), a0);
        a1 = __hfma2(u2b(w.y), u2b(v[j].y), a1);
        a2 = __hfma2(u2b(w.z), u2b(v[j].z), a2);
        a3 = __hfma2(u2b(w.w), u2b(v[j].w), a3);
    }
    __nv_bfloat162 s2 = __hadd2(__hadd2(a0, a1), __hadd2(a2, a3));
    float2 f = __bfloat1622float2(s2);
    return f.x + f.y;
}

// ---------------- persistent dataflow LSTM kernel ----------------
__global__ void __launch_bounds__(NTHR, 1) lstm_main(const float* __restrict__ x)
{
    extern __shared__ uint4 s_w4[];     // cached weight rows (k >= NRR)
    __shared__ uint4 s_v4[256];         // staged input vector (up to 2048 bf16)
    __shared__ float s_gates[128];
    __shared__ float s_bias[128];
    __shared__ float s_wih0[256];

    const int tid = threadIdx.x, lane = tid & 31, wid = tid >> 5;
    const int b = blockIdx.x;
    int layer, idx;
    if (b < NB0)             { layer = 0; idx = b; }
    else if (b < NB0+NB12)   { layer = 1; idx = b - NB0; }
    else                     { layer = 2; idx = b - (NB0+NB12); }

    int CH, hbase, R, rowU4, NBown, NBlow, boff, NRR;
    long long woff;
    if (layer == 0) {
        CH = 32; hbase = idx*32; R = 128; rowU4 = 128; NRR = 4;
        woff = (long long)idx*131072; boff = idx*128;
        NBown = NB0; NBlow = 0;
    } else {
        CH = (idx == NB12-1) ? 16 : 18; hbase = idx*18; R = 4*CH; rowU4 = 256; NRR = 2;
        woff = (long long)OFF1 + (long long)(layer-1)*SEG12 + (long long)idx*147456;
        boff = NB0*128 + (layer-1)*(NB12*72) + idx*72;
        NBown = NB12; NBlow = (layer == 1) ? NB0 : NB12;
    }
    const uint4* gw = (const uint4*)(g_wblob + woff);
    const uint4* hall4 = (const uint4*)g_hall;
    int* ownflags = &g_flag[layer*64*32];
    int* lowflags = &g_flag[(layer-1)*64*32];

    // one-time: stage rows [NRR*NW, R) into smem
    const int smU4 = (R - NRR*NW) * rowU4;
    for (int i2 = tid; i2 < smU4; i2 += NTHR) s_w4[i2] = gw[(size_t)NRR*NW*rowU4 + i2];
    if (tid < R) s_bias[tid] = g_bias[boff + tid];
    if (layer == 0 && tid < 256) s_wih0[tid] = g_wih0[idx*256 + tid];

    // one-time: register-cache rows wid + k*NW, k < NRR (64 regs both layers)
    uint4 wreg[16];
    if (layer == 0) {
#pragma unroll
        for (int k = 0; k < 4; k++)
#pragma unroll
            for (int j = 0; j < 4; j++)
                wreg[k*4+j] = gw[(size_t)(wid + k*NW)*128 + j*32 + lane];
    } else {
#pragma unroll
        for (int k = 0; k < 2; k++)
#pragma unroll
            for (int j = 0; j < 8; j++)
                wreg[k*8+j] = gw[(size_t)(wid + k*NW)*256 + j*32 + lane];
    }
    float creg = 0.0f;                  // cell state, lives in warp 11's regs
    __syncthreads();

    for (int t = 0; t < TT; ++t) {
        float x0 = 0.0f, x1 = 0.0f;
        if (layer == 0) { x0 = __ldg(&x[2*t]); x1 = __ldg(&x[2*t + 1]); }

        // ---- poll + stage fused: the polling warp stages its chunk itself ----
        if (layer == 0) {
            if (wid == 0) {
                wait_flags_pad(ownflags, NBown, t, lane);
                size_t ho = (size_t)t*384;
                s_v4[lane]      = hall4[ho + lane];
                s_v4[lane + 32] = hall4[ho + lane + 32];
                s_v4[lane + 64] = hall4[ho + lane + 64];
                s_v4[lane + 96] = hall4[ho + lane + 96];
            }
        } else {
            if (wid == 0) {
                wait_flags_pad(lowflags, NBlow, t + 1, lane);
                size_t lo = (size_t)(t+1)*384 + (size_t)(layer-1)*128;
                s_v4[lane]      = hall4[lo + lane];
                s_v4[lane + 32] = hall4[lo + lane + 32];
                s_v4[lane + 64] = hall4[lo + lane + 64];
                s_v4[lane + 96] = hall4[lo + lane + 96];
            } else if (wid == 1) {
                wait_flags_pad(ownflags, NBown, t, lane);
                size_t ho = (size_t)t*384 + (size_t)layer*128;
                s_v4[128 + lane]      = hall4[ho + lane];
                s_v4[128 + lane + 32] = hall4[ho + lane + 32];
                s_v4[128 + lane + 64] = hall4[ho + lane + 64];
                s_v4[128 + lane + 96] = hall4[ho + lane + 96];
            }
        }
        __syncthreads();   // A: deps satisfied + vector staged

        // ---- compute rows (batched dots, then ILP-interleaved reductions) ----
        if (layer == 0) {
            uint4 vv[4];
#pragma unroll
            for (int j = 0; j < 4; j++) vv[j] = s_v4[j*32 + lane];
            float ss[11];
#pragma unroll
            for (int k = 0; k < 4; k++)
                ss[k] = dot_rr<4>(&wreg[k*4], vv);
#pragma unroll
            for (int k = 4; k < 11; k++) {
                int r = wid + k*NW;
                ss[k] = (r < 128) ? dot_sm<4>(s_w4 + (size_t)(r - 4*NW)*128, lane, vv) : 0.0f;
            }
#pragma unroll
            for (int o = 16; o; o >>= 1)
#pragma unroll
                for (int k = 0; k < 11; k++)
                    ss[k] += __shfl_xor_sync(0xffffffffu, ss[k], o);
            if (lane == 0) {
#pragma unroll
                for (int k = 0; k < 11; k++) {
                    int r = wid + k*NW;
                    if (r < 128)
                        s_gates[r] = ss[k] + s_bias[r] + s_wih0[2*r]*x0 + s_wih0[2*r+1]*x1;
                }
            }
        } else {
            uint4 vv[8];
#pragma unroll
            for (int j = 0; j < 8; j++) vv[j] = s_v4[j*32 + lane];
            float ss[6];
            ss[0] = dot_rr<8>(&wreg[0], vv);
            ss[1] = dot_rr<8>(&wreg[8], vv);
#pragma unroll
            for (int k = 2; k < 6; k++) {
                int r = wid + k*NW;
                ss[k] = (r < R) ? dot_sm<8>(s_w4 + (size_t)(r - 2*NW)*256, lane, vv) : 0.0f;
            }
#pragma unroll
            for (int o = 16; o; o >>= 1)
#pragma unroll
                for (int k = 0; k < 6; k++)
                    ss[k] += __shfl_xor_sync(0xffffffffu, ss[k], o);
            if (lane == 0) {
#pragma unroll
                for (int k = 0; k < 6; k++) {
                    int r = wid + k*NW;
                    if (r < R) s_gates[r] = ss[k] + s_bias[r];
                }
            }
        }
        __syncthreads();   // B: gates ready

        // ---- pointwise + publish (warp 11, single publisher) ----
        if (wid == NW-1) {
            if (lane < CH) {
                float4 g = ((const float4*)s_gates)[lane];
                float ig = sigm(g.x);
                float fg = sigm(g.y);
                float gv = ftanh(g.z);
                float og = sigm(g.w);
                float c  = fg*creg + ig*gv;
                creg = c;
                g_hall[(size_t)(t+1)*3072 + (size_t)layer*1024 + hbase + lane] =
                    __float2bfloat16(og*ftanh(c));
            }
            __syncwarp();
            if (lane == 0) st_rel(&ownflags[idx*32], t + 1);
        }
    }
}

// ---------------- output head ----------------
__global__ void finalize_k(const float* __restrict__ Wres, const float* __restrict__ bres,
                           float* __restrict__ out)
{
    __shared__ float sred[4];
    const int t = blockIdx.x;
    const int tid = threadIdx.x;
    const __nv_bfloat16* h = g_hall + (size_t)(t+1)*3072 + 2048;
    float s = 0.0f;
    for (int k = tid; k < HD; k += 128) s += __bfloat162float(h[k]) * Wres[k];
#pragma unroll
    for (int o = 16; o; o >>= 1) s += __shfl_xor_sync(0xffffffffu, s, o);
    if ((tid & 31) == 0) sred[tid >> 5] = s;
    __syncthreads();
    if (tid == 0) {
        float tot = sred[0] + sred[1] + sred[2] + sred[3];
        out[t] = 1.0f/(1.0f + __expf(-(tot + bres[0])));
    }
}

// ---------------- launch ----------------
extern "C" void kernel_launch(void* const* d_in, const int* in_sizes, int n_in,
                              void* d_out, int out_size)
{
    const float* x     = (const float*)d_in[0];
    const float* Wih0  = (const float*)d_in[1];
    const float* Whh0  = (const float*)d_in[2];
    const float* bih0  = (const float*)d_in[3];
    const float* bhh0  = (const float*)d_in[4];
    const float* Wih12 = (const float*)d_in[5];
    const float* Whh12 = (const float*)d_in[6];
    const float* bih12 = (const float*)d_in[7];
    const float* bhh12 = (const float*)d_in[8];
    const float* Wres  = (const float*)d_in[9];
    const float* bres  = (const float*)d_in[10];
    float* out = (float*)d_out;

    cudaFuncSetAttribute(lstm_main, cudaFuncAttributeMaxDynamicSharedMemorySize, DSMEM_BYTES);

    prep_small<<<26, 256>>>(Wih0, bih0, bhh0, bih12, bhh12);
    prep_w<<<2048, 256>>>(Whh0, Wih12, Whh12);
    lstm_main<<<GRIDN, NTHR, DSMEM_BYTES>>>(x);
    finalize_k<<<TT, 128>>>(Wres, bres, out);
}

// round 10
// speedup vs baseline: 1.8472x; 1.0005x over previous
#include <cuda_runtime.h>
#include <cuda_bf16.h>
#include <stdint.h>

#define HD 1024
#define TT 4096
#define NB0 32
#define NB12 57
#define GRIDN (NB0 + 2*NB12)   /* 146 persistent blocks */
#define NTHR 384
#define NW 12                  /* warps per block */

#define OFF1 (NB0*128*1024)            /* 4194304  */
#define SEG12 (NB12*72*2048)           /* 8404992  */
#define OFF2 (OFF1 + SEG12)
#define WTOT (OFF1 + 2*SEG12)          /* 21004288 */

#define DSMEM_BYTES 204800             /* l12: 50 rows*4KB ; l0: 80 rows*2KB */

// ---------------- static device storage (no allocations) ----------------
__device__ __align__(16) __nv_bfloat16 g_wblob[WTOT];            // ~42 MB bf16 weights
__device__ float g_bias[NB0*128 + 2*NB12*72];
__device__ float g_wih0[NB0*128*2];
__device__ __align__(16) __nv_bfloat16 g_hall[(size_t)(TT+1)*3*HD]; // h history, write-once
__device__ __align__(128) int g_flag[3*64*32];                   // one 128B line per (layer,block)

__device__ __forceinline__ __nv_bfloat162 u2b(unsigned u) {
    return *reinterpret_cast<const __nv_bfloat162*>(&u);
}
__device__ __forceinline__ float sigm(float v)  { return __fdividef(1.0f, 1.0f + __expf(-v)); }
__device__ __forceinline__ float ftanh(float v) {
    v = fminf(fmaxf(v, -30.0f), 30.0f);
    float e = __expf(2.0f*v);
    return __fdividef(e - 1.0f, e + 1.0f);
}
__device__ __forceinline__ int ld_acq(const int* p) {
    int v; asm volatile("ld.acquire.gpu.s32 %0, [%1];" : "=r"(v) : "l"(p) : "memory"); return v;
}
__device__ __forceinline__ void st_rel(int* p, int v) {
    asm volatile("st.release.gpu.s32 [%0], %1;" :: "l"(p), "r"(v) : "memory");
}

// whole-warp wait: padded flags (stride 32 ints = 128B), each lane owns <=2 flags
__device__ __forceinline__ void wait_flags_pad(const int* base, int nb, int target, int lane) {
    const int* p0 = base + (size_t)(lane < nb ? lane : 0)*32;
    const int* p1 = base + (size_t)((lane + 32 < nb) ? (lane + 32) : 0)*32;
    for (;;) {
        int v = min(ld_acq(p0), ld_acq(p1));
        if (__all_sync(0xffffffffu, v >= target)) break;
    }
}

// ---------------- prep: repack weights into per-block bf16 blobs ----------------
__global__ void prep_w(const float* __restrict__ Whh0,
                       const float* __restrict__ Wih12,
                       const float* __restrict__ Whh12)
{
    for (long long i = (long long)blockIdx.x*blockDim.x + threadIdx.x; i < (long long)WTOT;
         i += (long long)gridDim.x*blockDim.x) {
        float val;
        if (i < (long long)OFF1) {
            int b   = (int)(i >> 17);
            int rem = (int)(i & 131071);
            int r   = rem >> 10;
            int col = rem & 1023;
            int grow = (r & 3)*HD + b*32 + (r >> 2);
            val = Whh0[(long long)grow*1024 + col];
        } else {
            int l = (i < (long long)OFF2) ? 0 : 1;
            long long j = i - (l ? (long long)OFF2 : (long long)OFF1);
            int b   = (int)(j / 147456);
            int rem = (int)(j % 147456);
            int r   = rem >> 11;
            int col = rem & 2047;
            int ih  = r >> 2;
            int CHb = (b == NB12-1) ? 16 : 18;
            if (ih >= CHb) val = 0.0f;
            else {
                int grow = (r & 3)*HD + b*18 + ih;
                if (col < 1024) val = Wih12[(long long)l*4194304 + (long long)grow*1024 + col];
                else            val = Whh12[(long long)l*4194304 + (long long)grow*1024 + (col-1024)];
            }
        }
        g_wblob[i] = __float2bfloat16(val);
    }
}

// ---------------- prep: biases, W_ih0, state/flag reset ----------------
__global__ void prep_small(const float* __restrict__ Wih0,
                           const float* __restrict__ bih0, const float* __restrict__ bhh0,
                           const float* __restrict__ bih12, const float* __restrict__ bhh12)
{
    int i = blockIdx.x*blockDim.x + threadIdx.x;
    int n = blockDim.x*gridDim.x;
    for (int k = i; k < 3*64*32; k += n) g_flag[k] = 0;
    for (int k = i; k < 3*HD; k += n) g_hall[k] = __float2bfloat16(0.0f);
    for (int k = i; k < NB0*128 + 2*NB12*72; k += n) {
        float v;
        if (k < NB0*128) {
            int b = k >> 7, r = k & 127;
            int grow = (r & 3)*HD + b*32 + (r >> 2);
            v = bih0[grow] + bhh0[grow];
        } else {
            int j  = k - NB0*128;
            int l  = j / (NB12*72);
            int jj = j - l*(NB12*72);
            int b  = jj / 72, r = jj % 72;
            int ih = r >> 2;
            int CHb = (b == NB12-1) ? 16 : 18;
            if (ih >= CHb) v = 0.0f;
            else {
                int grow = (r & 3)*HD + b*18 + ih;
                v = bih12[l*4096 + grow] + bhh12[l*4096 + grow];
            }
        }
        g_bias[k] = v;
    }
    for (int k = i; k < NB0*128*2; k += n) {
        int b = k >> 8;
        int r = (k >> 1) & 127;
        int c = k & 1;
        int grow = (r & 3)*HD + b*32 + (r >> 2);
        g_wih0[k] = Wih0[grow*2 + c];
    }
}

// ---------------- dot-product primitives (bf16x2 HFMA2) ----------------
template<int NJ>
__device__ __forceinline__ float dot_rr(const uint4* __restrict__ w, const uint4* __restrict__ v)
{
    __nv_bfloat162 z = __floats2bfloat162_rn(0.0f, 0.0f);
    __nv_bfloat162 a0 = z, a1 = z, a2 = z, a3 = z;
#pragma unroll
    for (int j = 0; j < NJ; j++) {
        a0 = __hfma2(u2b(w[j].x), u2b(v[j].x), a0);
        a1 = __hfma2(u2b(w[j].y), u2b(v[j].y), a1);
        a2 = __hfma2(u2b(w[j].z), u2b(v[j].z), a2);
        a3 = __hfma2(u2b(w[j].w), u2b(v[j].w), a3);
    }
    __nv_bfloat162 s2 = __hadd2(__hadd2(a0, a1), __hadd2(a2, a3));
    float2 f = __bfloat1622float2(s2);
    return f.x + f.y;
}

template<int NJ>
__device__ __forceinline__ float dot_sm(const uint4* __restrict__ wbase, int lane, const uint4* __restrict__ v)
{
    __nv_bfloat162 z = __floats2bfloat162_rn(0.0f, 0.0f);
    __nv_bfloat162 a0 = z, a1 = z, a2 = z, a3 = z;
#pragma unroll
    for (int j = 0; j < NJ; j++) {
        uint4 w = wbase[j*32 + lane];
        a0 = __hfma2(u2b(w.x), u2b(v[j].x), a0);
        a1 = __hfma2(u2b(w.y), u2b(v[j].y), a1);
        a2 = __hfma2(u2b(w.z), u2b(v[j].z), a2);
        a3 = __hfma2(u2b(w.w), u2b(v[j].w), a3);
    }
    __nv_bfloat162 s2 = __hadd2(__hadd2(a0, a1), __hadd2(a2, a3));
    float2 f = __bfloat1622float2(s2);
    return f.x + f.y;
}

// ---------------- persistent dataflow LSTM kernel (split-phase) ----------------
__global__ void __launch_bounds__(NTHR, 1) lstm_main(const float* __restrict__ x)
{
    extern __shared__ uint4 s_w4[];     // cached weight rows
    __shared__ uint4 s_v4[256];         // [0..127]=lower-h / own-h(l0), [128..255]=own-h
    __shared__ float s_gates[128];
    __shared__ float s_bias[128];
    __shared__ float s_wih0[256];

    const int tid = threadIdx.x, lane = tid & 31, wid = tid >> 5;
    const int b = blockIdx.x;
    int layer, idx;
    if (b < NB0)             { layer = 0; idx = b; }
    else if (b < NB0+NB12)   { layer = 1; idx = b - NB0; }
    else                     { layer = 2; idx = b - (NB0+NB12); }

    int CH, hbase, R, NBown, NBlow, boff;
    long long woff;
    if (layer == 0) {
        CH = 32; hbase = idx*32; R = 128;
        woff = (long long)idx*131072; boff = idx*128;
        NBown = NB0; NBlow = 0;
    } else {
        CH = (idx == NB12-1) ? 16 : 18; hbase = idx*18; R = 4*CH;
        woff = (long long)OFF1 + (long long)(layer-1)*SEG12 + (long long)idx*147456;
        boff = NB0*128 + (layer-1)*(NB12*72) + idx*72;
        NBown = NB12; NBlow = (layer == 1) ? NB0 : NB12;
    }
    const uint4* gw = (const uint4*)(g_wblob + woff);
    const uint4* hall4 = (const uint4*)g_hall;
    int* ownflags = &g_flag[layer*64*32];
    int* lowflags = &g_flag[(layer-1)*64*32];

    // compute-warp index: layer0 -> all 12 warps; l12 -> warps {0,2..11} (warp1 = own-poller)
    const int cw = (layer == 0) ? wid : ((wid == 0) ? 0 : wid - 1);
    const bool isc = (layer == 0) || (wid != 1);

    if (tid < R) s_bias[tid] = g_bias[boff + tid];
    if (layer == 0 && tid < 256) s_wih0[tid] = g_wih0[idx*256 + tid];

    // one-time weight staging
    uint4 wreg[16];
    if (layer == 0) {
        // 4 register rows: r = wid + k*12, k<4 ; smem rows k=4..10 at (k-4)*12+wid
#pragma unroll
        for (int k = 0; k < 4; k++)
#pragma unroll
            for (int j = 0; j < 4; j++)
                wreg[k*4+j] = gw[(size_t)(wid + k*NW)*128 + j*32 + lane];
        for (int k = 4; k < 11; k++) {
            int r = wid + k*NW;
            if (r < 128) {
                int s = (k-4)*NW + wid;
#pragma unroll
                for (int j = 0; j < 4; j++)
                    s_w4[(size_t)s*128 + j*32 + lane] = gw[(size_t)r*128 + j*32 + lane];
            }
        }
    } else if (isc) {
        // 2 register rows: r = cw + k*11, k<2 ; smem rows k=2..6 at (k-2)*11+cw
#pragma unroll
        for (int k = 0; k < 2; k++)
#pragma unroll
            for (int j = 0; j < 8; j++)
                wreg[k*8+j] = gw[(size_t)(cw + k*11)*256 + j*32 + lane];
        for (int k = 2; k < 7; k++) {
            int r = cw + k*11;
            if (r < R) {
                int s = (k-2)*11 + cw;
#pragma unroll
                for (int j = 0; j < 8; j++)
                    s_w4[(size_t)s*256 + j*32 + lane] = gw[(size_t)r*256 + j*32 + lane];
            }
        }
    }
    float creg = 0.0f;                  // cell state (warp 11's lanes)
    __syncthreads();

    for (int t = 0; t < TT; ++t) {
        if (layer == 0) {
            float x0 = __ldg(&x[2*t]), x1 = __ldg(&x[2*t + 1]);
            if (wid == 0) {
                wait_flags_pad(ownflags, NBown, t, lane);
                size_t ho = (size_t)t*384;
                s_v4[lane]      = hall4[ho + lane];
                s_v4[lane + 32] = hall4[ho + lane + 32];
                s_v4[lane + 64] = hall4[ho + lane + 64];
                s_v4[lane + 96] = hall4[ho + lane + 96];
            }
            __syncthreads();
            uint4 vv[4];
#pragma unroll
            for (int j = 0; j < 4; j++) vv[j] = s_v4[j*32 + lane];
            float ss[11];
#pragma unroll
            for (int k = 0; k < 4; k++)
                ss[k] = dot_rr<4>(&wreg[k*4], vv);
#pragma unroll
            for (int k = 4; k < 11; k++) {
                int r = wid + k*NW;
                ss[k] = (r < 128) ? dot_sm<4>(s_w4 + (size_t)((k-4)*NW + wid)*128, lane, vv) : 0.0f;
            }
#pragma unroll
            for (int o = 16; o; o >>= 1)
#pragma unroll
                for (int k = 0; k < 11; k++)
                    ss[k] += __shfl_xor_sync(0xffffffffu, ss[k], o);
            if (lane == 0) {
#pragma unroll
                for (int k = 0; k < 11; k++) {
                    int r = wid + k*NW;
                    if (r < 128)
                        s_gates[r] = ss[k] + s_bias[r] + s_wih0[2*r]*x0 + s_wih0[2*r+1]*x1;
                }
            }
            __syncthreads();
            if (wid == NW-1) {
                if (lane < CH) {
                    float4 g = ((const float4*)s_gates)[lane];
                    float c = sigm(g.y)*creg + sigm(g.x)*ftanh(g.z);
                    creg = c;
                    g_hall[(size_t)(t+1)*3072 + hbase + lane] =
                        __float2bfloat16(sigm(g.w)*ftanh(c));
                }
                __syncwarp();
                if (lane == 0) st_rel(&ownflags[idx*32], t + 1);
            }
        } else {
            float ss[7];
            // ---- phase A: lower-h staged by warp0, W_ih half; warp1 fetches own-h ----
            if (wid == 0) {
                wait_flags_pad(lowflags, NBlow, t + 1, lane);
                size_t lo = (size_t)(t+1)*384 + (size_t)(layer-1)*128;
                s_v4[lane]      = hall4[lo + lane];
                s_v4[lane + 32] = hall4[lo + lane + 32];
                s_v4[lane + 64] = hall4[lo + lane + 64];
                s_v4[lane + 96] = hall4[lo + lane + 96];
                asm volatile("bar.sync 1, 352;" ::: "memory");
            } else if (wid >= 2) {
                asm volatile("bar.sync 1, 352;" ::: "memory");
            } else { // wid == 1: own-h poller/stager (no rows)
                wait_flags_pad(ownflags, NBown, t, lane);
                size_t ho = (size_t)t*384 + (size_t)layer*128;
                s_v4[128 + lane]      = hall4[ho + lane];
                s_v4[128 + lane + 32] = hall4[ho + lane + 32];
                s_v4[128 + lane + 64] = hall4[ho + lane + 64];
                s_v4[128 + lane + 96] = hall4[ho + lane + 96];
            }
            if (isc) {
                uint4 vv[4];
#pragma unroll
                for (int j = 0; j < 4; j++) vv[j] = s_v4[j*32 + lane];
                ss[0] = dot_rr<4>(&wreg[0], vv);
                ss[1] = dot_rr<4>(&wreg[8], vv);
#pragma unroll
                for (int k = 2; k < 7; k++) {
                    int r = cw + k*11;
                    ss[k] = (r < R) ? dot_sm<4>(s_w4 + (size_t)((k-2)*11 + cw)*256, lane, vv) : 0.0f;
                }
            }
            __syncthreads();   // B: own-h staged + phase A done
            // ---- phase B: W_hh half (recurrence-critical) ----
            if (isc) {
                uint4 vv[4];
#pragma unroll
                for (int j = 0; j < 4; j++) vv[j] = s_v4[128 + j*32 + lane];
                ss[0] += dot_rr<4>(&wreg[4], vv);
                ss[1] += dot_rr<4>(&wreg[12], vv);
#pragma unroll
                for (int k = 2; k < 7; k++) {
                    int r = cw + k*11;
                    if (r < R)
                        ss[k] += dot_sm<4>(s_w4 + (size_t)((k-2)*11 + cw)*256 + 128, lane, vv);
                }
#pragma unroll
                for (int o = 16; o; o >>= 1)
#pragma unroll
                    for (int k = 0; k < 7; k++)
                        ss[k] += __shfl_xor_sync(0xffffffffu, ss[k], o);
                if (lane == 0) {
#pragma unroll
                    for (int k = 0; k < 7; k++) {
                        int r = cw + k*11;
                        if (r < R) s_gates[r] = ss[k] + s_bias[r];
                    }
                }
            }
            __syncthreads();   // C: gates ready
            if (wid == NW-1) {
                if (lane < CH) {
                    float4 g = ((const float4*)s_gates)[lane];
                    float c = sigm(g.y)*creg + sigm(g.x)*ftanh(g.z);
                    creg = c;
                    g_hall[(size_t)(t+1)*3072 + (size_t)layer*1024 + hbase + lane] =
                        __float2bfloat16(sigm(g.w)*ftanh(c));
                }
                __syncwarp();
                if (lane == 0) st_rel(&ownflags[idx*32], t + 1);
            }
        }
    }
}

// ---------------- output head ----------------
__global__ void finalize_k(const float* __restrict__ Wres, const float* __restrict__ bres,
                           float* __restrict__ out)
{
    __shared__ float sred[4];
    const int t = blockIdx.x;
    const int tid = threadIdx.x;
    const __nv_bfloat16* h = g_hall + (size_t)(t+1)*3072 + 2048;
    float s = 0.0f;
    for (int k = tid; k < HD; k += 128) s += __bfloat162float(h[k]) * Wres[k];
#pragma unroll
    for (int o = 16; o; o >>= 1) s += __shfl_xor_sync(0xffffffffu, s, o);
    if ((tid & 31) == 0) sred[tid >> 5] = s;
    __syncthreads();
    if (tid == 0) {
        float tot = sred[0] + sred[1] + sred[2] + sred[3];
        out[t] = 1.0f/(1.0f + __expf(-(tot + bres[0])));
    }
}

// ---------------- launch ----------------
extern "C" void kernel_launch(void* const* d_in, const int* in_sizes, int n_in,
                              void* d_out, int out_size)
{
    const float* x     = (const float*)d_in[0];
    const float* Wih0  = (const float*)d_in[1];
    const float* Whh0  = (const float*)d_in[2];
    const float* bih0  = (const float*)d_in[3];
    const float* bhh0  = (const float*)d_in[4];
    const float* Wih12 = (const float*)d_in[5];
    const float* Whh12 = (const float*)d_in[6];
    const float* bih12 = (const float*)d_in[7];
    const float* bhh12 = (const float*)d_in[8];
    const float* Wres  = (const float*)d_in[9];
    const float* bres  = (const float*)d_in[10];
    float* out = (float*)d_out;

    cudaFuncSetAttribute(lstm_main, cudaFuncAttributeMaxDynamicSharedMemorySize, DSMEM_BYTES);

    prep_small<<<26, 256>>>(Wih0, bih0, bhh0, bih12, bhh12);
    prep_w<<<2048, 256>>>(Whh0, Wih12, Whh12);
    lstm_main<<<GRIDN, NTHR, DSMEM_BYTES>>>(x);
    finalize_k<<<TT, 128>>>(Wres, bres, out);
}